// round 13
// baseline (speedup 1.0000x reference)
#include <cuda_runtime.h>
#include <math.h>

#define RUNS 512
#define WAYS 5
#define SHOT 5
#define NSUP 25
#define NQ   75
#define N100 100
#define N105 105
#define DIM  640
#define LAMv 10.0f
#define EPSV 0.001f
#define MAXIT 1000
#define TPW 130

typedef unsigned long long u64t;
__device__ __forceinline__ u64t pk2(float lo, float hi){
    u64t r; asm("mov.b64 %0,{%1,%2};" : "=l"(r) : "f"(lo), "f"(hi)); return r;
}
__device__ __forceinline__ float2 upk2(u64t v){
    float2 r; asm("mov.b64 {%0,%1},%2;" : "=f"(r.x), "=f"(r.y) : "l"(v)); return r;
}
__device__ __forceinline__ void ffma2(u64t &acc, u64t a, u64t b){
    asm("fma.rn.f32x2 %0,%1,%2,%0;" : "+l"(acc) : "l"(a), "l"(b));
}

__device__ float g_ap[(size_t)RUNS*WAYS*DIM];
__device__ float g_proto[(size_t)RUNS*WAYS*DIM];
__device__ float g_M[(size_t)RUNS*NQ*WAYS];
__device__ float g_Z[(size_t)RUNS*N105*WAYS];
__device__ int   g_bad[4*1024];

__device__ __forceinline__ float wredSum(float v){
    #pragma unroll
    for (int o=16;o;o>>=1) v += __shfl_xor_sync(0xffffffffu, v, o);
    return v;
}

// ================= sinkhorn device routines (warp-collective) =============
template<int N, int NL>
__device__ __forceinline__ void sink_phaseA(const float* __restrict__ in,
                                            const int* __restrict__ ysb,
                                            int* __restrict__ badp, int lane){
    constexpr int J = (N+31)/32;
    const float cval = (float)(N/WAYS);
    float p[J][WAYS]; bool valid[J];
    #pragma unroll
    for (int j=0;j<J;j++){
        int r = lane+32*j; valid[j] = (r<N);
        #pragma unroll
        for (int k=0;k<WAYS;k++) p[j][k] = valid[j] ? in[r*WAYS+k] : 0.0f;
    }
    int ycls = 0;
    const bool pin = (NL>0) && (lane < NL);
    if (pin) ycls = ysb[lane];
    float u[J];
    #pragma unroll
    for (int j=0;j<J;j++) u[j]=0.0f;
    int streak = 0;
    for (int t=0; t<MAXIT; t++){
        float rs[J]; float dvl = 0.0f;
        #pragma unroll
        for (int j=0;j<J;j++){
            rs[j] = p[j][0]+p[j][1]+p[j][2]+p[j][3]+p[j][4];
            if (valid[j]) dvl = fmaxf(dvl, fabsf(u[j]-rs[j]));
            u[j] = rs[j];
        }
        #pragma unroll
        for (int j=0;j<J;j++) if (valid[j]){
            float f = 1.0f/rs[j];
            #pragma unroll
            for (int k=0;k<WAYS;k++) p[j][k] *= f;
        }
        float cs[WAYS];
        #pragma unroll
        for (int k=0;k<WAYS;k++){
            float a = 0.0f;
            #pragma unroll
            for (int j=0;j<J;j++) if (valid[j]) a += p[j][k];
            cs[k] = a;
        }
        #pragma unroll
        for (int o=16;o;o>>=1){
            dvl = fmaxf(dvl, __shfl_xor_sync(0xffffffffu, dvl, o));
            #pragma unroll
            for (int k=0;k<WAYS;k++) cs[k] += __shfl_xor_sync(0xffffffffu, cs[k], o);
        }
        #pragma unroll
        for (int k=0;k<WAYS;k++){
            float f = cval/cs[k];
            #pragma unroll
            for (int j=0;j<J;j++) if (valid[j]) p[j][k] *= f;
        }
        if (pin){
            #pragma unroll
            for (int k=0;k<WAYS;k++) p[0][k] = (k==ycls)?1.0f:0.0f;
        }
        if (dvl > EPSV){ if (lane==0) badp[t] = 1; streak = 0; }
        else if (++streak >= 12) break;
    }
}

template<int N, int NL>
__device__ __forceinline__ void sink_phaseB(const float* __restrict__ in,
                                            const int* __restrict__ ysb,
                                            const int* __restrict__ badp, int lane,
                                            float (&p)[(N+31)/32][WAYS]){
    constexpr int J = (N+31)/32;
    const float cval = (float)(N/WAYS);
    bool valid[J];
    #pragma unroll
    for (int j=0;j<J;j++){
        int r = lane+32*j; valid[j] = (r<N);
        #pragma unroll
        for (int k=0;k<WAYS;k++) p[j][k] = valid[j] ? in[r*WAYS+k] : 0.0f;
    }
    int ycls = 0;
    const bool pin = (NL>0) && (lane < NL);
    if (pin) ycls = ysb[lane];
    int myT = MAXIT;
    for (int t=lane; t<MAXIT; t+=32) if (badp[t]==0) myT = min(myT, t);
    #pragma unroll
    for (int o=16;o;o>>=1) myT = min(myT, __shfl_xor_sync(0xffffffffu, myT, o));
    const int T = myT;
    for (int t=0; t<T; t++){
        float rs[J];
        #pragma unroll
        for (int j=0;j<J;j++){
            rs[j] = p[j][0]+p[j][1]+p[j][2]+p[j][3]+p[j][4];
            if (valid[j]){
                float f = 1.0f/rs[j];
                #pragma unroll
                for (int k=0;k<WAYS;k++) p[j][k] *= f;
            }
        }
        float cs[WAYS];
        #pragma unroll
        for (int k=0;k<WAYS;k++){
            float a = 0.0f;
            #pragma unroll
            for (int j=0;j<J;j++) if (valid[j]) a += p[j][k];
            cs[k] = a;
        }
        #pragma unroll
        for (int o=16;o;o>>=1){
            #pragma unroll
            for (int k=0;k<WAYS;k++) cs[k] += __shfl_xor_sync(0xffffffffu, cs[k], o);
        }
        #pragma unroll
        for (int k=0;k<WAYS;k++){
            float f = cval/cs[k];
            #pragma unroll
            for (int j=0;j<J;j++) if (valid[j]) p[j][k] *= f;
        }
        if (pin){
            #pragma unroll
            for (int k=0;k<WAYS;k++) p[0][k] = (k==ycls)?1.0f:0.0f;
        }
    }
}

// ================= K: zero bad flags ======================================
__global__ void k_zero(){
    int tid = threadIdx.x;
    for (int t=tid; t<4*1024; t+=256) g_bad[t]=0;
}

// ================= K: proto init + dist(e0) + sinkA75(slot0) ==============
__global__ void __launch_bounds__(256) k_front(const float* __restrict__ xs,
                                               const float* __restrict__ xq){
    __shared__ float sp[WAYS*DIM];
    __shared__ float pn[WAYS];
    __shared__ float Msm[NQ*WAYS];
    int b = blockIdx.x, tid = threadIdx.x;
    int w = tid>>5, lane = tid&31;
    const float* s0 = xs + (size_t)b*NSUP*DIM;
    float* pr = g_proto + (size_t)b*WAYS*DIM;
    for (int t=tid; t<WAYS*DIM; t+=256){
        int ww = t/DIM, d = t-ww*DIM;
        float a = 0.f;
        #pragma unroll
        for (int s=0;s<SHOT;s++) a += s0[(ww*SHOT+s)*DIM + d];
        float v = a*0.2f;
        sp[t] = v; pr[t] = v;
    }
    __syncthreads();
    if (w < WAYS){
        float a=0.f;
        for (int d=lane; d<DIM; d+=32){ float v=sp[w*DIM+d]; a += v*v; }
        a = wredSum(a);
        if (lane==0) pn[w]=a;
    }
    __syncthreads();
    const float* xqb = xq + (size_t)b*NQ*DIM;
    for (int r=w; r<NQ; r+=8){
        const float* f = xqb + (size_t)r*DIM;
        float nf=0.f, dk[WAYS]={0,0,0,0,0};
        for (int d=lane; d<DIM; d+=32){
            float v = f[d];
            nf += v*v;
            #pragma unroll
            for (int k=0;k<WAYS;k++) dk[k] += v*sp[k*DIM+d];
        }
        #pragma unroll
        for (int o=16;o;o>>=1){
            nf += __shfl_xor_sync(0xffffffffu, nf, o);
            #pragma unroll
            for (int k=0;k<WAYS;k++) dk[k] += __shfl_xor_sync(0xffffffffu, dk[k], o);
        }
        if (lane < WAYS){
            float d2 = fmaxf(nf + pn[lane] - 2.0f*dk[lane], 0.0f);
            float m = __expf(-LAMv*d2);
            Msm[r*WAYS+lane] = m;
            g_M[((size_t)b*NQ + r)*WAYS + lane] = m;
        }
    }
    __syncthreads();
    if (w==0) sink_phaseA<NQ,0>(Msm, (const int*)0, g_bad + 0*1024, lane);
}

// ===== K: sinkB75(slot_in) + update (+dist + sinkA75(slot_out) if !full) ===
__global__ void __launch_bounds__(256) k_mid(const float* __restrict__ xs,
                                             const float* __restrict__ xq,
                                             const int* __restrict__ ys,
                                             int slot_in, int slot_out, int full){
    __shared__ __align__(16) float z8[N100][8];
    __shared__ float zq[376];
    __shared__ float entm[N100];
    __shared__ float S[WAYS];
    __shared__ float sp[WAYS*DIM];
    __shared__ float pn[WAYS];
    __shared__ float Msm[NQ*WAYS];
    __shared__ float dpd[WAYS*WAYS];
    __shared__ float dpe[WAYS*WAYS];
    __shared__ float maskv[WAYS];
    __shared__ float omega_s;
    int b = blockIdx.x, tid = threadIdx.x;
    int w = tid>>5, lane = tid&31;
    const float INVLOG5 = 0.6213349345596119f;

    if (w==0){
        float p[(NQ+31)/32][WAYS];
        sink_phaseB<NQ,0>(g_M + (size_t)b*NQ*WAYS, (const int*)0,
                          g_bad + slot_in*1024, lane, p);
        #pragma unroll
        for (int j=0;j<(NQ+31)/32;j++){
            int r = lane+32*j;
            if (r<NQ){
                #pragma unroll
                for (int k=0;k<WAYS;k++) zq[r*WAYS+k] = p[j][k];
            }
        }
    }
    __syncthreads();

    if (tid < N100){
        float zv[WAYS];
        if (tid < NSUP){
            int c = ys[b*NSUP + tid];
            #pragma unroll
            for (int k=0;k<WAYS;k++) zv[k] = (k==c)?1.0f:0.0f;
        } else {
            #pragma unroll
            for (int k=0;k<WAYS;k++) zv[k] = zq[(tid-NSUP)*WAYS+k];
        }
        float q[WAYS]; float s = 0.0f;
        #pragma unroll
        for (int k=0;k<WAYS;k++){ q[k] = zv[k] + 1e-12f; s += q[k]; }
        float H = 0.0f;
        #pragma unroll
        for (int k=0;k<WAYS;k++){ float pp = q[k]/s; H -= pp*logf(pp); }
        float e = H*INVLOG5;
        entm[tid] = e;
        float wgt = 1.0f - e;
        #pragma unroll
        for (int k=0;k<WAYS;k++) z8[tid][k] = zv[k]*wgt;
        z8[tid][5]=0.f; z8[tid][6]=0.f; z8[tid][7]=0.f;
    }
    __syncthreads();
    if (tid < WAYS){
        float a = 0.0f;
        for (int i=0;i<N100;i++) a += z8[i][tid];
        S[tid] = a;
    }
    if (tid == 128){
        float a = 0.0f;
        for (int i=0;i<N100;i++) a += entm[i];
        omega_s = a*0.01f;
    }
    __syncthreads();
    const float* xsb = xs + (size_t)b*NSUP*DIM;
    const float* xqb = xq + (size_t)b*NQ*DIM;
    float* prb = g_proto + (size_t)b*WAYS*DIM;
    for (int d=tid; d<DIM; d+=256){
        float acc[WAYS] = {0,0,0,0,0};
        #pragma unroll 5
        for (int i=0;i<NSUP;i++){
            float f = xsb[(size_t)i*DIM + d];
            float4 zv = *(const float4*)&z8[i][0];
            float z4 = z8[i][4];
            acc[0] += zv.x*f; acc[1] += zv.y*f; acc[2] += zv.z*f;
            acc[3] += zv.w*f; acc[4] += z4*f;
        }
        #pragma unroll 5
        for (int i=0;i<NQ;i++){
            float f = xqb[(size_t)i*DIM + d];
            float4 zv = *(const float4*)&z8[NSUP+i][0];
            float z4 = z8[NSUP+i][4];
            acc[0] += zv.x*f; acc[1] += zv.y*f; acc[2] += zv.z*f;
            acc[3] += zv.w*f; acc[4] += z4*f;
        }
        #pragma unroll
        for (int k=0;k<WAYS;k++){
            float pv = 0.4f*prb[k*DIM+d] + 0.6f*(acc[k]/S[k]);
            prb[k*DIM+d] = pv;
            sp[k*DIM+d]  = pv;
        }
    }
    __syncthreads();

    if (full){
        for (int pidx=w; pidx<WAYS*WAYS; pidx+=8){
            int a = pidx/WAYS, c = pidx%WAYS;
            float acc = 0.0f;
            for (int d=lane; d<DIM; d+=32) acc += sp[a*DIM+d]*sp[c*DIM+d];
            acc = wredSum(acc);
            if (lane==0) dpd[pidx] = acc;
        }
        __syncthreads();
        if (tid < WAYS*WAYS){
            int a = tid/WAYS, c = tid%WAYS;
            float d2 = fmaxf(dpd[a*WAYS+a] + dpd[c*WAYS+c] - 2.0f*dpd[tid], 0.0f);
            dpe[tid] = __expf(-LAMv*d2);
        }
        __syncthreads();
        if (tid < WAYS){
            float q[WAYS]; float s = 0.0f;
            #pragma unroll
            for (int k=0;k<WAYS;k++){ q[k] = dpe[tid*WAYS+k] + 1e-12f; s += q[k]; }
            float H = 0.0f;
            #pragma unroll
            for (int k=0;k<WAYS;k++){ float pp = q[k]/s; H -= pp*logf(pp); }
            maskv[tid] = (H*INVLOG5 < omega_s) ? 1.0f : 0.0f;
        }
        __syncthreads();
        float* Zb = g_Z + (size_t)b*N105*WAYS;
        float* fwr = g_ap + (size_t)b*WAYS*DIM;
        for (int t=tid; t<WAYS*DIM; t+=256) fwr[t] = sp[t]*maskv[t/DIM];
        for (int t=tid; t<N100*WAYS; t+=256) Zb[t] = z8[t/WAYS][t%WAYS];
        if (tid < WAYS*WAYS) Zb[N100*WAYS + tid] = dpe[tid]*maskv[tid/WAYS];
        return;
    }

    if (w < WAYS){
        float a=0.f;
        for (int d=lane; d<DIM; d+=32){ float v=sp[w*DIM+d]; a += v*v; }
        a = wredSum(a);
        if (lane==0) pn[w]=a;
    }
    __syncthreads();
    for (int r=w; r<NQ; r+=8){
        const float* f = xqb + (size_t)r*DIM;
        float nf=0.f, dk[WAYS]={0,0,0,0,0};
        for (int d=lane; d<DIM; d+=32){
            float v = f[d];
            nf += v*v;
            #pragma unroll
            for (int k=0;k<WAYS;k++) dk[k] += v*sp[k*DIM+d];
        }
        #pragma unroll
        for (int o=16;o;o>>=1){
            nf += __shfl_xor_sync(0xffffffffu, nf, o);
            #pragma unroll
            for (int k=0;k<WAYS;k++) dk[k] += __shfl_xor_sync(0xffffffffu, dk[k], o);
        }
        if (lane < WAYS){
            float d2 = fmaxf(nf + pn[lane] - 2.0f*dk[lane], 0.0f);
            float m = __expf(-LAMv*d2);
            Msm[r*WAYS+lane] = m;
            g_M[((size_t)b*NQ + r)*WAYS + lane] = m;
        }
    }
    __syncthreads();
    if (w==0) sink_phaseA<NQ,0>(Msm, (const int*)0, g_bad + slot_out*1024, lane);
}

// ====== K: fused Gram(FFMA2) -> W -> A=I-aW -> blocked LU + sinkA105 ======
__global__ void __launch_bounds__(256) k_solve(const float* __restrict__ xs,
                                               const float* __restrict__ xq,
                                               const int* __restrict__ ys){
    __shared__ float As[N105*N105];    // 44100 B; front aliased as tile[64*TPW]
    __shared__ float zz[N105*WAYS];
    __shared__ float nrm[112];
    __shared__ float dm[N105];
    int b = blockIdx.x, tid = threadIdx.x;
    int w = tid>>5, lane = tid&31;
    int tx = tid & 15, ty = tid >> 4;
    const float* xsb = xs + (size_t)b*NSUP*DIM;
    const float* xqb = xq + (size_t)b*NQ*DIM;
    const float* apg = g_ap + (size_t)b*WAYS*DIM;

    // ---- Gram over all 105 rows, FFMA2, tile aliased into As ----
    float* tile = As;                      // 64*TPW = 8320 floats
    u64t acc2[7][4];
    #pragma unroll
    for (int i=0;i<7;i++)
        #pragma unroll
        for (int e=0;e<4;e++) acc2[i][e] = pk2(0.f,0.f);
    for (int t=tid; t<64*TPW; t+=256) tile[t]=0.f;
    __syncthreads();
    for (int c=0;c<10;c++){
        for (int t=tid; t<N105*64; t+=256){
            int row = t>>6, k = t&63;
            const float* fr = (row<NSUP) ? (xsb + (size_t)row*DIM)
                            : (row<N100) ? (xqb + (size_t)(row-NSUP)*DIM)
                                         : (apg + (size_t)(row-N100)*DIM);
            tile[k*TPW+row] = fr[c*64+k];
        }
        __syncthreads();
        #pragma unroll 2
        for (int k=0;k<64;k++){
            const float* tk = &tile[k*TPW];
            u64t ap[7], bp[4];
            #pragma unroll
            for (int i=0;i<7;i++){ float a = tk[ty+16*i]; ap[i]=pk2(a,a); }
            #pragma unroll
            for (int e=0;e<4;e++){
                float2 bv = *(const float2*)(tk + 2*tx + 32*e);
                bp[e] = pk2(bv.x, bv.y);
            }
            #pragma unroll
            for (int i=0;i<7;i++)
                #pragma unroll
                for (int e=0;e<4;e++) ffma2(acc2[i][e], ap[i], bp[e]);
        }
        __syncthreads();
    }
    // diagonal norms
    #pragma unroll
    for (int i=0;i<7;i++){
        int r = ty+16*i;
        #pragma unroll
        for (int e=0;e<4;e++){
            int c = 2*tx+32*e;
            if (c==r || c+1==r){
                float2 g = upk2(acc2[i][e]);
                if (c==r)   nrm[r] = g.x;
                if (c+1==r) nrm[r] = g.y;
            }
        }
    }
    __syncthreads();
    // W = exp(-lam d2) into As (diag 0); overwrites tile region (no more reads)
    #pragma unroll
    for (int i=0;i<7;i++){
        int r = ty+16*i;
        if (r < N105){
            float nr = nrm[r];
            #pragma unroll
            for (int e=0;e<4;e++){
                int c = 2*tx+32*e;
                float2 g = upk2(acc2[i][e]);
                if (c < N105){
                    float d2 = fmaxf(nr+nrm[c]-2.0f*g.x, 0.0f);
                    As[r*N105+c] = (r==c)?0.0f:__expf(-LAMv*d2);
                }
                if (c+1 < N105){
                    float d2 = fmaxf(nr+nrm[c+1]-2.0f*g.y, 0.0f);
                    As[r*N105+c+1] = (r==c+1)?0.0f:__expf(-LAMv*d2);
                }
            }
        }
    }
    float* Zb = g_Z + (size_t)b*N105*WAYS;
    for (int t=tid; t<N105*WAYS; t+=256) zz[t] = Zb[t];
    __syncthreads();

    if (tid < N105){
        float s = 0.0f;
        for (int j=0;j<N105;j++) s += As[tid*N105+j];
        dm[tid] = rsqrtf(s);
    }
    __syncthreads();
    for (int t=tid; t<N105*N105; t+=256){
        int i = t/N105, j = t - i*N105;
        As[t] = ((i==j)?1.0f:0.0f) - 0.7f*dm[i]*dm[j]*As[t];
    }
    __syncthreads();

    // ---- rank-4 blocked LU forward elimination ----
    for (int K=0; K<26; K++){
        const int k0 = 4*K;
        if (w==0){
            #pragma unroll
            for (int kk=0; kk<4; kk++){
                int pc = k0+kk;
                float inv = 1.0f/As[pc*N105+pc];
                for (int i=pc+1+lane; i<N105; i+=32){
                    float l = As[i*N105+pc]*inv;
                    As[i*N105+pc] = l;
                    #pragma unroll
                    for (int c=kk+1; c<4; c++)
                        As[i*N105+k0+c] -= l*As[pc*N105+k0+c];
                }
                __syncwarp();
            }
        }
        __syncthreads();
        float l10=As[(k0+1)*N105+k0];
        float l20=As[(k0+2)*N105+k0], l21=As[(k0+2)*N105+k0+1];
        float l30=As[(k0+3)*N105+k0], l31=As[(k0+3)*N105+k0+1], l32=As[(k0+3)*N105+k0+2];
        for (int j=k0+4+tid; j<N105; j+=256){
            float a0=As[(k0+0)*N105+j], a1=As[(k0+1)*N105+j];
            float a2=As[(k0+2)*N105+j], a3=As[(k0+3)*N105+j];
            a1 -= l10*a0;
            a2 -= l20*a0 + l21*a1;
            a3 -= l30*a0 + l31*a1 + l32*a2;
            As[(k0+1)*N105+j]=a1; As[(k0+2)*N105+j]=a2; As[(k0+3)*N105+j]=a3;
        }
        if (tid < WAYS){
            float a0=zz[(k0+0)*WAYS+tid], a1=zz[(k0+1)*WAYS+tid];
            float a2=zz[(k0+2)*WAYS+tid], a3=zz[(k0+3)*WAYS+tid];
            a1 -= l10*a0;
            a2 -= l20*a0 + l21*a1;
            a3 -= l30*a0 + l31*a1 + l32*a2;
            zz[(k0+1)*WAYS+tid]=a1; zz[(k0+2)*WAYS+tid]=a2; zz[(k0+3)*WAYS+tid]=a3;
        }
        __syncthreads();
        const int j0 = k0+4+lane;
        float u0[4], u1[4], u2[4], u3[4], uz0,uz1,uz2,uz3;
        #pragma unroll
        for (int e=0;e<4;e++){
            int j = j0+32*e;
            bool ok = (j<N105);
            u0[e] = ok ? As[(k0+0)*N105+j] : 0.0f;
            u1[e] = ok ? As[(k0+1)*N105+j] : 0.0f;
            u2[e] = ok ? As[(k0+2)*N105+j] : 0.0f;
            u3[e] = ok ? As[(k0+3)*N105+j] : 0.0f;
        }
        uz0 = (lane<WAYS)? zz[(k0+0)*WAYS+lane] : 0.0f;
        uz1 = (lane<WAYS)? zz[(k0+1)*WAYS+lane] : 0.0f;
        uz2 = (lane<WAYS)? zz[(k0+2)*WAYS+lane] : 0.0f;
        uz3 = (lane<WAYS)? zz[(k0+3)*WAYS+lane] : 0.0f;
        for (int i=k0+4+w; i<N105; i+=8){
            float l0=As[i*N105+k0+0], l1=As[i*N105+k0+1];
            float l2=As[i*N105+k0+2], l3=As[i*N105+k0+3];
            #pragma unroll
            for (int e=0;e<4;e++){
                int j = j0+32*e;
                if (j<N105)
                    As[i*N105+j] -= l0*u0[e]+l1*u1[e]+l2*u2[e]+l3*u3[e];
            }
            if (lane<WAYS)
                zz[i*WAYS+lane] -= l0*uz0+l1*uz1+l2*uz2+l3*uz3;
        }
        __syncthreads();
    }

    // ---- blocked back substitution ----
    if (tid < WAYS) zz[104*WAYS+tid] /= As[104*N105+104];
    __syncthreads();
    for (int t=tid; t<104*WAYS; t+=256){
        int i=t/WAYS, m=t-i*WAYS;
        zz[t] -= As[i*N105+104]*zz[104*WAYS+m];
    }
    __syncthreads();
    for (int K=25; K>=0; K--){
        const int lo = 4*K, hi = lo+3;
        if (w==0 && lane<WAYS){
            for (int r=hi; r>=lo; r--){
                float acc = zz[r*WAYS+lane];
                for (int c=r+1; c<=hi; c++) acc -= As[r*N105+c]*zz[c*WAYS+lane];
                zz[r*WAYS+lane] = acc / As[r*N105+r];
            }
        }
        __syncthreads();
        if (lo > 0){
            for (int t=tid; t<lo*WAYS; t+=256){
                int i=t/WAYS, m=t-i*WAYS;
                float s = As[i*N105+lo+0]*zz[(lo+0)*WAYS+m]
                        + As[i*N105+lo+1]*zz[(lo+1)*WAYS+m]
                        + As[i*N105+lo+2]*zz[(lo+2)*WAYS+m]
                        + As[i*N105+lo+3]*zz[(lo+3)*WAYS+m];
                zz[t] -= s;
            }
        }
        __syncthreads();
    }
    for (int t=tid; t<N105*WAYS; t+=256) Zb[t] = zz[t];
    __syncthreads();
    if (w==0) sink_phaseA<N105,NSUP>(zz, ys + b*NSUP, g_bad + 3*1024, lane);
}

// ================= K: sinkB105(slot3) + accuracy ==========================
__global__ void __launch_bounds__(128) k_final(const int* __restrict__ ys,
                                               const int* __restrict__ yq,
                                               float* __restrict__ out){
    int gw = blockIdx.x*4 + (threadIdx.x>>5);
    int lane = threadIdx.x & 31;
    if (gw >= RUNS) return;
    int b = gw;
    float p[(N105+31)/32][WAYS];
    sink_phaseB<N105,NSUP>(g_Z + (size_t)b*N105*WAYS, ys + b*NSUP,
                           g_bad + 3*1024, lane, p);
    int cnt = 0;
    #pragma unroll
    for (int j=0;j<(N105+31)/32;j++){
        int r = lane + 32*j;
        if (r >= NSUP && r < N100){
            float best = p[j][0]; int bi = 0;
            #pragma unroll
            for (int k=1;k<WAYS;k++){ if (p[j][k] > best){ best = p[j][k]; bi = k; } }
            cnt += (bi == yq[b*NQ + (r-NSUP)]) ? 1 : 0;
        }
    }
    #pragma unroll
    for (int o=16;o;o>>=1) cnt += __shfl_xor_sync(0xffffffffu, cnt, o);
    if (lane==0) out[b] = (float)cnt / 75.0f;
}

extern "C" void kernel_launch(void* const* d_in, const int* in_sizes, int n_in,
                              void* d_out, int out_size){
    const float* xs = (const float*)d_in[0];
    const float* xq = (const float*)d_in[1];
    const int*   ys = (const int*)d_in[2];
    const int*   yq = (const int*)d_in[3];
    float* out = (float*)d_out;
    (void)in_sizes; (void)n_in; (void)out_size;

    k_zero<<<1,256>>>();                                   // 0
    k_front<<<RUNS,256>>>(xs, xq);                         // 1
    k_mid<<<RUNS,256>>>(xs, xq, ys, 0, 1, 0);              // 2
    k_mid<<<RUNS,256>>>(xs, xq, ys, 1, 2, 0);              // 3
    k_mid<<<RUNS,256>>>(xs, xq, ys, 2, 0, 1);              // 4
    k_solve<<<RUNS,256>>>(xs, xq, ys);                     // 5: gram+W+LU+sinkA105
    k_final<<<RUNS/4,128>>>(ys, yq, out);                  // 6
}

// round 14
// speedup vs baseline: 1.1318x; 1.1318x over previous
#include <cuda_runtime.h>
#include <math.h>

#define RUNS 512
#define WAYS 5
#define SHOT 5
#define NSUP 25
#define NQ   75
#define N100 100
#define N105 105
#define DIM  640
#define LAMv 10.0f
#define EPSV 0.001f
#define MAXIT 1000
#define TPW 130

typedef unsigned long long u64t;
__device__ __forceinline__ u64t pk2(float lo, float hi){
    u64t r; asm("mov.b64 %0,{%1,%2};" : "=l"(r) : "f"(lo), "f"(hi)); return r;
}
__device__ __forceinline__ float2 upk2(u64t v){
    float2 r; asm("mov.b64 {%0,%1},%2;" : "=f"(r.x), "=f"(r.y) : "l"(v)); return r;
}
__device__ __forceinline__ void ffma2(u64t &acc, u64t a, u64t b){
    asm("fma.rn.f32x2 %0,%1,%2,%0;" : "+l"(acc) : "l"(a), "l"(b));
}

__device__ float g_ap[(size_t)RUNS*WAYS*DIM];
__device__ float g_proto[(size_t)RUNS*WAYS*DIM];
__device__ float g_M[(size_t)RUNS*NQ*WAYS];
__device__ float g_Z[(size_t)RUNS*N105*WAYS];
__device__ float g_E105[(size_t)RUNS*N105*N105];
__device__ int   g_bad[4*1024];

__device__ __forceinline__ float wredSum(float v){
    #pragma unroll
    for (int o=16;o;o>>=1) v += __shfl_xor_sync(0xffffffffu, v, o);
    return v;
}

// ================= sinkhorn device routines (warp-collective) =============
template<int N, int NL>
__device__ __forceinline__ void sink_phaseA(const float* __restrict__ in,
                                            const int* __restrict__ ysb,
                                            int* __restrict__ badp, int lane){
    constexpr int J = (N+31)/32;
    const float cval = (float)(N/WAYS);
    float p[J][WAYS]; bool valid[J];
    #pragma unroll
    for (int j=0;j<J;j++){
        int r = lane+32*j; valid[j] = (r<N);
        #pragma unroll
        for (int k=0;k<WAYS;k++) p[j][k] = valid[j] ? in[r*WAYS+k] : 0.0f;
    }
    int ycls = 0;
    const bool pin = (NL>0) && (lane < NL);
    if (pin) ycls = ysb[lane];
    float u[J];
    #pragma unroll
    for (int j=0;j<J;j++) u[j]=0.0f;
    int streak = 0;
    for (int t=0; t<MAXIT; t++){
        float rs[J]; float dvl = 0.0f;
        #pragma unroll
        for (int j=0;j<J;j++){
            rs[j] = p[j][0]+p[j][1]+p[j][2]+p[j][3]+p[j][4];
            if (valid[j]) dvl = fmaxf(dvl, fabsf(u[j]-rs[j]));
            u[j] = rs[j];
        }
        #pragma unroll
        for (int j=0;j<J;j++) if (valid[j]){
            float f = 1.0f/rs[j];
            #pragma unroll
            for (int k=0;k<WAYS;k++) p[j][k] *= f;
        }
        float cs[WAYS];
        #pragma unroll
        for (int k=0;k<WAYS;k++){
            float a = 0.0f;
            #pragma unroll
            for (int j=0;j<J;j++) if (valid[j]) a += p[j][k];
            cs[k] = a;
        }
        #pragma unroll
        for (int o=16;o;o>>=1){
            dvl = fmaxf(dvl, __shfl_xor_sync(0xffffffffu, dvl, o));
            #pragma unroll
            for (int k=0;k<WAYS;k++) cs[k] += __shfl_xor_sync(0xffffffffu, cs[k], o);
        }
        #pragma unroll
        for (int k=0;k<WAYS;k++){
            float f = cval/cs[k];
            #pragma unroll
            for (int j=0;j<J;j++) if (valid[j]) p[j][k] *= f;
        }
        if (pin){
            #pragma unroll
            for (int k=0;k<WAYS;k++) p[0][k] = (k==ycls)?1.0f:0.0f;
        }
        if (dvl > EPSV){ if (lane==0) badp[t] = 1; streak = 0; }
        else if (++streak >= 12) break;
    }
}

template<int N, int NL>
__device__ __forceinline__ void sink_phaseB(const float* __restrict__ in,
                                            const int* __restrict__ ysb,
                                            const int* __restrict__ badp, int lane,
                                            float (&p)[(N+31)/32][WAYS]){
    constexpr int J = (N+31)/32;
    const float cval = (float)(N/WAYS);
    bool valid[J];
    #pragma unroll
    for (int j=0;j<J;j++){
        int r = lane+32*j; valid[j] = (r<N);
        #pragma unroll
        for (int k=0;k<WAYS;k++) p[j][k] = valid[j] ? in[r*WAYS+k] : 0.0f;
    }
    int ycls = 0;
    const bool pin = (NL>0) && (lane < NL);
    if (pin) ycls = ysb[lane];
    int myT = MAXIT;
    for (int t=lane; t<MAXIT; t+=32) if (badp[t]==0) myT = min(myT, t);
    #pragma unroll
    for (int o=16;o;o>>=1) myT = min(myT, __shfl_xor_sync(0xffffffffu, myT, o));
    const int T = myT;
    for (int t=0; t<T; t++){
        float rs[J];
        #pragma unroll
        for (int j=0;j<J;j++){
            rs[j] = p[j][0]+p[j][1]+p[j][2]+p[j][3]+p[j][4];
            if (valid[j]){
                float f = 1.0f/rs[j];
                #pragma unroll
                for (int k=0;k<WAYS;k++) p[j][k] *= f;
            }
        }
        float cs[WAYS];
        #pragma unroll
        for (int k=0;k<WAYS;k++){
            float a = 0.0f;
            #pragma unroll
            for (int j=0;j<J;j++) if (valid[j]) a += p[j][k];
            cs[k] = a;
        }
        #pragma unroll
        for (int o=16;o;o>>=1){
            #pragma unroll
            for (int k=0;k<WAYS;k++) cs[k] += __shfl_xor_sync(0xffffffffu, cs[k], o);
        }
        #pragma unroll
        for (int k=0;k<WAYS;k++){
            float f = cval/cs[k];
            #pragma unroll
            for (int j=0;j<J;j++) if (valid[j]) p[j][k] *= f;
        }
        if (pin){
            #pragma unroll
            for (int k=0;k<WAYS;k++) p[0][k] = (k==ycls)?1.0f:0.0f;
        }
    }
}

// ================= K: zero bad flags ======================================
__global__ void k_zero(){
    int tid = threadIdx.x;
    for (int t=tid; t<4*1024; t+=256) g_bad[t]=0;
}

// ================= K: proto init + dist(e0) + sinkA75(slot0) ==============
__global__ void __launch_bounds__(256) k_front(const float* __restrict__ xs,
                                               const float* __restrict__ xq){
    __shared__ float sp[WAYS*DIM];
    __shared__ float pn[WAYS];
    __shared__ float Msm[NQ*WAYS];
    int b = blockIdx.x, tid = threadIdx.x;
    int w = tid>>5, lane = tid&31;
    const float* s0 = xs + (size_t)b*NSUP*DIM;
    float* pr = g_proto + (size_t)b*WAYS*DIM;
    for (int t=tid; t<WAYS*DIM; t+=256){
        int ww = t/DIM, d = t-ww*DIM;
        float a = 0.f;
        #pragma unroll
        for (int s=0;s<SHOT;s++) a += s0[(ww*SHOT+s)*DIM + d];
        float v = a*0.2f;
        sp[t] = v; pr[t] = v;
    }
    __syncthreads();
    if (w < WAYS){
        float a=0.f;
        for (int d=lane; d<DIM; d+=32){ float v=sp[w*DIM+d]; a += v*v; }
        a = wredSum(a);
        if (lane==0) pn[w]=a;
    }
    __syncthreads();
    const float* xqb = xq + (size_t)b*NQ*DIM;
    for (int r=w; r<NQ; r+=8){
        const float* f = xqb + (size_t)r*DIM;
        float nf=0.f, dk[WAYS]={0,0,0,0,0};
        #pragma unroll 4
        for (int d=lane; d<DIM; d+=32){
            float v = f[d];
            nf += v*v;
            #pragma unroll
            for (int k=0;k<WAYS;k++) dk[k] += v*sp[k*DIM+d];
        }
        #pragma unroll
        for (int o=16;o;o>>=1){
            nf += __shfl_xor_sync(0xffffffffu, nf, o);
            #pragma unroll
            for (int k=0;k<WAYS;k++) dk[k] += __shfl_xor_sync(0xffffffffu, dk[k], o);
        }
        if (lane < WAYS){
            float d2 = fmaxf(nf + pn[lane] - 2.0f*dk[lane], 0.0f);
            float m = __expf(-LAMv*d2);
            Msm[r*WAYS+lane] = m;
            g_M[((size_t)b*NQ + r)*WAYS + lane] = m;
        }
    }
    __syncthreads();
    if (w==0) sink_phaseA<NQ,0>(Msm, (const int*)0, g_bad + 0*1024, lane);
}

// ===== K: sinkB75(slot_in) + update (+dist + sinkA75(slot_out) if !full) ===
__global__ void __launch_bounds__(256) k_mid(const float* __restrict__ xs,
                                             const float* __restrict__ xq,
                                             const int* __restrict__ ys,
                                             int slot_in, int slot_out, int full){
    __shared__ __align__(16) float z8[N100][8];
    __shared__ float zq[376];
    __shared__ float entm[N100];
    __shared__ float S[WAYS];
    __shared__ float sp[WAYS*DIM];
    __shared__ float pn[WAYS];
    __shared__ float Msm[NQ*WAYS];
    __shared__ float dpd[WAYS*WAYS];
    __shared__ float dpe[WAYS*WAYS];
    __shared__ float maskv[WAYS];
    __shared__ float omega_s;
    int b = blockIdx.x, tid = threadIdx.x;
    int w = tid>>5, lane = tid&31;
    const float INVLOG5 = 0.6213349345596119f;

    if (w==0){
        float p[(NQ+31)/32][WAYS];
        sink_phaseB<NQ,0>(g_M + (size_t)b*NQ*WAYS, (const int*)0,
                          g_bad + slot_in*1024, lane, p);
        #pragma unroll
        for (int j=0;j<(NQ+31)/32;j++){
            int r = lane+32*j;
            if (r<NQ){
                #pragma unroll
                for (int k=0;k<WAYS;k++) zq[r*WAYS+k] = p[j][k];
            }
        }
    }
    __syncthreads();

    if (tid < N100){
        float zv[WAYS];
        if (tid < NSUP){
            int c = ys[b*NSUP + tid];
            #pragma unroll
            for (int k=0;k<WAYS;k++) zv[k] = (k==c)?1.0f:0.0f;
        } else {
            #pragma unroll
            for (int k=0;k<WAYS;k++) zv[k] = zq[(tid-NSUP)*WAYS+k];
        }
        float q[WAYS]; float s = 0.0f;
        #pragma unroll
        for (int k=0;k<WAYS;k++){ q[k] = zv[k] + 1e-12f; s += q[k]; }
        float H = 0.0f;
        #pragma unroll
        for (int k=0;k<WAYS;k++){ float pp = q[k]/s; H -= pp*logf(pp); }
        float e = H*INVLOG5;
        entm[tid] = e;
        float wgt = 1.0f - e;
        #pragma unroll
        for (int k=0;k<WAYS;k++) z8[tid][k] = zv[k]*wgt;
        z8[tid][5]=0.f; z8[tid][6]=0.f; z8[tid][7]=0.f;
    }
    __syncthreads();
    if (tid < WAYS){
        float a = 0.0f;
        for (int i=0;i<N100;i++) a += z8[i][tid];
        S[tid] = a;
    }
    if (tid == 128){
        float a = 0.0f;
        for (int i=0;i<N100;i++) a += entm[i];
        omega_s = a*0.01f;
    }
    __syncthreads();
    const float* xsb = xs + (size_t)b*NSUP*DIM;
    const float* xqb = xq + (size_t)b*NQ*DIM;
    float* prb = g_proto + (size_t)b*WAYS*DIM;
    for (int d=tid; d<DIM; d+=256){
        float acc[WAYS] = {0,0,0,0,0};
        #pragma unroll 5
        for (int i=0;i<NSUP;i++){
            float f = xsb[(size_t)i*DIM + d];
            float4 zv = *(const float4*)&z8[i][0];
            float z4 = z8[i][4];
            acc[0] += zv.x*f; acc[1] += zv.y*f; acc[2] += zv.z*f;
            acc[3] += zv.w*f; acc[4] += z4*f;
        }
        #pragma unroll 15
        for (int i=0;i<NQ;i++){
            float f = xqb[(size_t)i*DIM + d];
            float4 zv = *(const float4*)&z8[NSUP+i][0];
            float z4 = z8[NSUP+i][4];
            acc[0] += zv.x*f; acc[1] += zv.y*f; acc[2] += zv.z*f;
            acc[3] += zv.w*f; acc[4] += z4*f;
        }
        #pragma unroll
        for (int k=0;k<WAYS;k++){
            float pv = 0.4f*prb[k*DIM+d] + 0.6f*(acc[k]/S[k]);
            prb[k*DIM+d] = pv;
            sp[k*DIM+d]  = pv;
        }
    }
    __syncthreads();

    if (full){
        for (int pidx=w; pidx<WAYS*WAYS; pidx+=8){
            int a = pidx/WAYS, c = pidx%WAYS;
            float acc = 0.0f;
            for (int d=lane; d<DIM; d+=32) acc += sp[a*DIM+d]*sp[c*DIM+d];
            acc = wredSum(acc);
            if (lane==0) dpd[pidx] = acc;
        }
        __syncthreads();
        if (tid < WAYS*WAYS){
            int a = tid/WAYS, c = tid%WAYS;
            float d2 = fmaxf(dpd[a*WAYS+a] + dpd[c*WAYS+c] - 2.0f*dpd[tid], 0.0f);
            dpe[tid] = __expf(-LAMv*d2);
        }
        __syncthreads();
        if (tid < WAYS){
            float q[WAYS]; float s = 0.0f;
            #pragma unroll
            for (int k=0;k<WAYS;k++){ q[k] = dpe[tid*WAYS+k] + 1e-12f; s += q[k]; }
            float H = 0.0f;
            #pragma unroll
            for (int k=0;k<WAYS;k++){ float pp = q[k]/s; H -= pp*logf(pp); }
            maskv[tid] = (H*INVLOG5 < omega_s) ? 1.0f : 0.0f;
        }
        __syncthreads();
        float* Zb = g_Z + (size_t)b*N105*WAYS;
        float* fwr = g_ap + (size_t)b*WAYS*DIM;
        for (int t=tid; t<WAYS*DIM; t+=256) fwr[t] = sp[t]*maskv[t/DIM];
        for (int t=tid; t<N100*WAYS; t+=256) Zb[t] = z8[t/WAYS][t%WAYS];
        if (tid < WAYS*WAYS) Zb[N100*WAYS + tid] = dpe[tid]*maskv[tid/WAYS];
        return;
    }

    if (w < WAYS){
        float a=0.f;
        for (int d=lane; d<DIM; d+=32){ float v=sp[w*DIM+d]; a += v*v; }
        a = wredSum(a);
        if (lane==0) pn[w]=a;
    }
    __syncthreads();
    for (int r=w; r<NQ; r+=8){
        const float* f = xqb + (size_t)r*DIM;
        float nf=0.f, dk[WAYS]={0,0,0,0,0};
        #pragma unroll 4
        for (int d=lane; d<DIM; d+=32){
            float v = f[d];
            nf += v*v;
            #pragma unroll
            for (int k=0;k<WAYS;k++) dk[k] += v*sp[k*DIM+d];
        }
        #pragma unroll
        for (int o=16;o;o>>=1){
            nf += __shfl_xor_sync(0xffffffffu, nf, o);
            #pragma unroll
            for (int k=0;k<WAYS;k++) dk[k] += __shfl_xor_sync(0xffffffffu, dk[k], o);
        }
        if (lane < WAYS){
            float d2 = fmaxf(nf + pn[lane] - 2.0f*dk[lane], 0.0f);
            float m = __expf(-LAMv*d2);
            Msm[r*WAYS+lane] = m;
            g_M[((size_t)b*NQ + r)*WAYS + lane] = m;
        }
    }
    __syncthreads();
    if (w==0) sink_phaseA<NQ,0>(Msm, (const int*)0, g_bad + slot_out*1024, lane);
}

// ====== K: full 105x105 W = exp(-lam d2) cache (FFMA2, separate kernel) ====
__global__ void __launch_bounds__(256) k_gram105(const float* __restrict__ xs,
                                                 const float* __restrict__ xq){
    __shared__ float tile[64*TPW];
    __shared__ float nd[112];
    int b = blockIdx.x, tid = threadIdx.x;
    int tx = tid & 15, ty = tid >> 4;
    u64t acc2[7][4];
    #pragma unroll
    for (int i=0;i<7;i++)
        #pragma unroll
        for (int e=0;e<4;e++) acc2[i][e] = pk2(0.f,0.f);
    for (int t=tid; t<64*TPW; t+=256) tile[t]=0.f;
    __syncthreads();
    const float* xsb = xs + (size_t)b*NSUP*DIM;
    const float* xqb = xq + (size_t)b*NQ*DIM;
    const float* apg = g_ap + (size_t)b*WAYS*DIM;
    for (int c=0;c<10;c++){
        for (int t=tid; t<N105*64; t+=256){
            int row = t>>6, k = t&63;
            const float* fr = (row<NSUP) ? (xsb + (size_t)row*DIM)
                            : (row<N100) ? (xqb + (size_t)(row-NSUP)*DIM)
                                         : (apg + (size_t)(row-N100)*DIM);
            tile[k*TPW+row] = fr[c*64+k];
        }
        __syncthreads();
        #pragma unroll 2
        for (int k=0;k<64;k++){
            const float* tk = &tile[k*TPW];
            u64t ap[7], bp[4];
            #pragma unroll
            for (int i=0;i<7;i++){ float a = tk[ty+16*i]; ap[i]=pk2(a,a); }
            #pragma unroll
            for (int e=0;e<4;e++){
                float2 bv = *(const float2*)(tk + 2*tx + 32*e);
                bp[e] = pk2(bv.x, bv.y);
            }
            #pragma unroll
            for (int i=0;i<7;i++)
                #pragma unroll
                for (int e=0;e<4;e++) ffma2(acc2[i][e], ap[i], bp[e]);
        }
        __syncthreads();
    }
    #pragma unroll
    for (int i=0;i<7;i++){
        int r = ty+16*i;
        #pragma unroll
        for (int e=0;e<4;e++){
            int c = 2*tx+32*e;
            if (c==r || c+1==r){
                float2 g = upk2(acc2[i][e]);
                if (c==r)   nd[r] = g.x;
                if (c+1==r) nd[r] = g.y;
            }
        }
    }
    __syncthreads();
    float* E = g_E105 + (size_t)b*N105*N105;
    #pragma unroll
    for (int i=0;i<7;i++){
        int r = ty+16*i;
        if (r < N105){
            float nr = nd[r];
            #pragma unroll
            for (int e=0;e<4;e++){
                int c = 2*tx+32*e;
                float2 g = upk2(acc2[i][e]);
                if (c < N105){
                    float d2 = fmaxf(nr+nd[c]-2.0f*g.x, 0.0f);
                    E[r*N105+c] = (r==c)?0.0f:__expf(-LAMv*d2);
                }
                if (c+1 < N105){
                    float d2 = fmaxf(nr+nd[c+1]-2.0f*g.y, 0.0f);
                    E[r*N105+c+1] = (r==c+1)?0.0f:__expf(-LAMv*d2);
                }
            }
        }
    }
}

// ====== K: E105 -> A=I-aW -> blocked LU solve + sinkA105(slot3) ============
__global__ void __launch_bounds__(256) k_solve(const int* __restrict__ ys){
    __shared__ float As[N105*N105];
    __shared__ float zz[N105*WAYS];
    __shared__ float dm[N105];
    int b = blockIdx.x, tid = threadIdx.x;
    int w = tid>>5, lane = tid&31;

    const float* E = g_E105 + (size_t)b*N105*N105;
    for (int t=tid; t<N105*N105; t+=256) As[t] = E[t];
    float* Zb = g_Z + (size_t)b*N105*WAYS;
    for (int t=tid; t<N105*WAYS; t+=256) zz[t] = Zb[t];
    __syncthreads();

    if (tid < N105){
        float s = 0.0f;
        for (int j=0;j<N105;j++) s += As[tid*N105+j];
        dm[tid] = rsqrtf(s);
    }
    __syncthreads();
    for (int t=tid; t<N105*N105; t+=256){
        int i = t/N105, j = t - i*N105;
        As[t] = ((i==j)?1.0f:0.0f) - 0.7f*dm[i]*dm[j]*As[t];
    }
    __syncthreads();

    // ---- rank-4 blocked LU forward elimination ----
    for (int K=0; K<26; K++){
        const int k0 = 4*K;
        if (w==0){
            #pragma unroll
            for (int kk=0; kk<4; kk++){
                int pc = k0+kk;
                float inv = 1.0f/As[pc*N105+pc];
                for (int i=pc+1+lane; i<N105; i+=32){
                    float l = As[i*N105+pc]*inv;
                    As[i*N105+pc] = l;
                    #pragma unroll
                    for (int c=kk+1; c<4; c++)
                        As[i*N105+k0+c] -= l*As[pc*N105+k0+c];
                }
                __syncwarp();
            }
        }
        __syncthreads();
        float l10=As[(k0+1)*N105+k0];
        float l20=As[(k0+2)*N105+k0], l21=As[(k0+2)*N105+k0+1];
        float l30=As[(k0+3)*N105+k0], l31=As[(k0+3)*N105+k0+1], l32=As[(k0+3)*N105+k0+2];
        for (int j=k0+4+tid; j<N105; j+=256){
            float a0=As[(k0+0)*N105+j], a1=As[(k0+1)*N105+j];
            float a2=As[(k0+2)*N105+j], a3=As[(k0+3)*N105+j];
            a1 -= l10*a0;
            a2 -= l20*a0 + l21*a1;
            a3 -= l30*a0 + l31*a1 + l32*a2;
            As[(k0+1)*N105+j]=a1; As[(k0+2)*N105+j]=a2; As[(k0+3)*N105+j]=a3;
        }
        if (tid < WAYS){
            float a0=zz[(k0+0)*WAYS+tid], a1=zz[(k0+1)*WAYS+tid];
            float a2=zz[(k0+2)*WAYS+tid], a3=zz[(k0+3)*WAYS+tid];
            a1 -= l10*a0;
            a2 -= l20*a0 + l21*a1;
            a3 -= l30*a0 + l31*a1 + l32*a2;
            zz[(k0+1)*WAYS+tid]=a1; zz[(k0+2)*WAYS+tid]=a2; zz[(k0+3)*WAYS+tid]=a3;
        }
        __syncthreads();
        const int j0 = k0+4+lane;
        float u0[4], u1[4], u2[4], u3[4], uz0,uz1,uz2,uz3;
        #pragma unroll
        for (int e=0;e<4;e++){
            int j = j0+32*e;
            bool ok = (j<N105);
            u0[e] = ok ? As[(k0+0)*N105+j] : 0.0f;
            u1[e] = ok ? As[(k0+1)*N105+j] : 0.0f;
            u2[e] = ok ? As[(k0+2)*N105+j] : 0.0f;
            u3[e] = ok ? As[(k0+3)*N105+j] : 0.0f;
        }
        uz0 = (lane<WAYS)? zz[(k0+0)*WAYS+lane] : 0.0f;
        uz1 = (lane<WAYS)? zz[(k0+1)*WAYS+lane] : 0.0f;
        uz2 = (lane<WAYS)? zz[(k0+2)*WAYS+lane] : 0.0f;
        uz3 = (lane<WAYS)? zz[(k0+3)*WAYS+lane] : 0.0f;
        for (int i=k0+4+w; i<N105; i+=8){
            float l0=As[i*N105+k0+0], l1=As[i*N105+k0+1];
            float l2=As[i*N105+k0+2], l3=As[i*N105+k0+3];
            #pragma unroll
            for (int e=0;e<4;e++){
                int j = j0+32*e;
                if (j<N105)
                    As[i*N105+j] -= l0*u0[e]+l1*u1[e]+l2*u2[e]+l3*u3[e];
            }
            if (lane<WAYS)
                zz[i*WAYS+lane] -= l0*uz0+l1*uz1+l2*uz2+l3*uz3;
        }
        __syncthreads();
    }

    // ---- blocked back substitution ----
    if (tid < WAYS) zz[104*WAYS+tid] /= As[104*N105+104];
    __syncthreads();
    for (int t=tid; t<104*WAYS; t+=256){
        int i=t/WAYS, m=t-i*WAYS;
        zz[t] -= As[i*N105+104]*zz[104*WAYS+m];
    }
    __syncthreads();
    for (int K=25; K>=0; K--){
        const int lo = 4*K, hi = lo+3;
        if (w==0 && lane<WAYS){
            for (int r=hi; r>=lo; r--){
                float acc = zz[r*WAYS+lane];
                for (int c=r+1; c<=hi; c++) acc -= As[r*N105+c]*zz[c*WAYS+lane];
                zz[r*WAYS+lane] = acc / As[r*N105+r];
            }
        }
        __syncthreads();
        if (lo > 0){
            for (int t=tid; t<lo*WAYS; t+=256){
                int i=t/WAYS, m=t-i*WAYS;
                float s = As[i*N105+lo+0]*zz[(lo+0)*WAYS+m]
                        + As[i*N105+lo+1]*zz[(lo+1)*WAYS+m]
                        + As[i*N105+lo+2]*zz[(lo+2)*WAYS+m]
                        + As[i*N105+lo+3]*zz[(lo+3)*WAYS+m];
                zz[t] -= s;
            }
        }
        __syncthreads();
    }
    for (int t=tid; t<N105*WAYS; t+=256) Zb[t] = zz[t];
    __syncthreads();
    if (w==0) sink_phaseA<N105,NSUP>(zz, ys + b*NSUP, g_bad + 3*1024, lane);
}

// ================= K: sinkB105(slot3) + accuracy ==========================
__global__ void __launch_bounds__(128) k_final(const int* __restrict__ ys,
                                               const int* __restrict__ yq,
                                               float* __restrict__ out){
    int gw = blockIdx.x*4 + (threadIdx.x>>5);
    int lane = threadIdx.x & 31;
    if (gw >= RUNS) return;
    int b = gw;
    float p[(N105+31)/32][WAYS];
    sink_phaseB<N105,NSUP>(g_Z + (size_t)b*N105*WAYS, ys + b*NSUP,
                           g_bad + 3*1024, lane, p);
    int cnt = 0;
    #pragma unroll
    for (int j=0;j<(N105+31)/32;j++){
        int r = lane + 32*j;
        if (r >= NSUP && r < N100){
            float best = p[j][0]; int bi = 0;
            #pragma unroll
            for (int k=1;k<WAYS;k++){ if (p[j][k] > best){ best = p[j][k]; bi = k; } }
            cnt += (bi == yq[b*NQ + (r-NSUP)]) ? 1 : 0;
        }
    }
    #pragma unroll
    for (int o=16;o;o>>=1) cnt += __shfl_xor_sync(0xffffffffu, cnt, o);
    if (lane==0) out[b] = (float)cnt / 75.0f;
}

extern "C" void kernel_launch(void* const* d_in, const int* in_sizes, int n_in,
                              void* d_out, int out_size){
    const float* xs = (const float*)d_in[0];
    const float* xq = (const float*)d_in[1];
    const int*   ys = (const int*)d_in[2];
    const int*   yq = (const int*)d_in[3];
    float* out = (float*)d_out;
    (void)in_sizes; (void)n_in; (void)out_size;

    k_zero<<<1,256>>>();                                   // 0
    k_front<<<RUNS,256>>>(xs, xq);                         // 1
    k_mid<<<RUNS,256>>>(xs, xq, ys, 0, 1, 0);              // 2
    k_mid<<<RUNS,256>>>(xs, xq, ys, 1, 2, 0);              // 3
    k_mid<<<RUNS,256>>>(xs, xq, ys, 2, 0, 1);              // 4
    k_gram105<<<RUNS,256>>>(xs, xq);                       // 5: full W cache
    k_solve<<<RUNS,256>>>(ys);                             // 6: A + LU + sinkA105
    k_final<<<RUNS/4,128>>>(ys, yq, out);                  // 7
}

// round 15
// speedup vs baseline: 1.8408x; 1.6264x over previous
#include <cuda_runtime.h>
#include <math.h>

#define RUNS 512
#define WAYS 5
#define SHOT 5
#define NSUP 25
#define NQ   75
#define N100 100
#define N105 105
#define DIM  640
#define LAMv 10.0f
#define EPSV 0.001f
#define MAXIT 1000
#define TPW 130

typedef unsigned long long u64t;
__device__ __forceinline__ u64t pk2(float lo, float hi){
    u64t r; asm("mov.b64 %0,{%1,%2};" : "=l"(r) : "f"(lo), "f"(hi)); return r;
}
__device__ __forceinline__ float2 upk2(u64t v){
    float2 r; asm("mov.b64 {%0,%1},%2;" : "=f"(r.x), "=f"(r.y) : "l"(v)); return r;
}
__device__ __forceinline__ void ffma2(u64t &acc, u64t a, u64t b){
    asm("fma.rn.f32x2 %0,%1,%2,%0;" : "+l"(acc) : "l"(a), "l"(b));
}

__device__ float g_G[(size_t)RUNS*N100*N100];    // raw Gram dots (epoch-invariant)
__device__ float g_C[(size_t)RUNS*N100*WAYS];    // proto coefficients
__device__ float g_S[(size_t)RUNS*N105*WAYS];    // strip dots + P' block
__device__ float g_M[(size_t)RUNS*NQ*WAYS];
__device__ float g_Z[(size_t)RUNS*N105*WAYS];
__device__ int   g_bad[4*1024];

// ================= sinkhorn device routines (warp-collective) =============
template<int N, int NL>
__device__ __forceinline__ void sink_phaseA(const float* __restrict__ in,
                                            const int* __restrict__ ysb,
                                            int* __restrict__ badp, int lane){
    constexpr int J = (N+31)/32;
    const float cval = (float)(N/WAYS);
    float p[J][WAYS]; bool valid[J];
    #pragma unroll
    for (int j=0;j<J;j++){
        int r = lane+32*j; valid[j] = (r<N);
        #pragma unroll
        for (int k=0;k<WAYS;k++) p[j][k] = valid[j] ? in[r*WAYS+k] : 0.0f;
    }
    int ycls = 0;
    const bool pin = (NL>0) && (lane < NL);
    if (pin) ycls = ysb[lane];
    float u[J];
    #pragma unroll
    for (int j=0;j<J;j++) u[j]=0.0f;
    int streak = 0;
    for (int t=0; t<MAXIT; t++){
        float rs[J]; float dvl = 0.0f;
        #pragma unroll
        for (int j=0;j<J;j++){
            rs[j] = p[j][0]+p[j][1]+p[j][2]+p[j][3]+p[j][4];
            if (valid[j]) dvl = fmaxf(dvl, fabsf(u[j]-rs[j]));
            u[j] = rs[j];
        }
        #pragma unroll
        for (int j=0;j<J;j++) if (valid[j]){
            float f = 1.0f/rs[j];
            #pragma unroll
            for (int k=0;k<WAYS;k++) p[j][k] *= f;
        }
        float cs[WAYS];
        #pragma unroll
        for (int k=0;k<WAYS;k++){
            float a = 0.0f;
            #pragma unroll
            for (int j=0;j<J;j++) if (valid[j]) a += p[j][k];
            cs[k] = a;
        }
        #pragma unroll
        for (int o=16;o;o>>=1){
            dvl = fmaxf(dvl, __shfl_xor_sync(0xffffffffu, dvl, o));
            #pragma unroll
            for (int k=0;k<WAYS;k++) cs[k] += __shfl_xor_sync(0xffffffffu, cs[k], o);
        }
        #pragma unroll
        for (int k=0;k<WAYS;k++){
            float f = cval/cs[k];
            #pragma unroll
            for (int j=0;j<J;j++) if (valid[j]) p[j][k] *= f;
        }
        if (pin){
            #pragma unroll
            for (int k=0;k<WAYS;k++) p[0][k] = (k==ycls)?1.0f:0.0f;
        }
        if (dvl > EPSV){ if (lane==0) badp[t] = 1; streak = 0; }
        else if (++streak >= 12) break;
    }
}

template<int N, int NL>
__device__ __forceinline__ void sink_phaseB(const float* __restrict__ in,
                                            const int* __restrict__ ysb,
                                            const int* __restrict__ badp, int lane,
                                            float (&p)[(N+31)/32][WAYS]){
    constexpr int J = (N+31)/32;
    const float cval = (float)(N/WAYS);
    bool valid[J];
    #pragma unroll
    for (int j=0;j<J;j++){
        int r = lane+32*j; valid[j] = (r<N);
        #pragma unroll
        for (int k=0;k<WAYS;k++) p[j][k] = valid[j] ? in[r*WAYS+k] : 0.0f;
    }
    int ycls = 0;
    const bool pin = (NL>0) && (lane < NL);
    if (pin) ycls = ysb[lane];
    int myT = MAXIT;
    for (int t=lane; t<MAXIT; t+=32) if (badp[t]==0) myT = min(myT, t);
    #pragma unroll
    for (int o=16;o;o>>=1) myT = min(myT, __shfl_xor_sync(0xffffffffu, myT, o));
    const int T = myT;
    for (int t=0; t<T; t++){
        float rs[J];
        #pragma unroll
        for (int j=0;j<J;j++){
            rs[j] = p[j][0]+p[j][1]+p[j][2]+p[j][3]+p[j][4];
            if (valid[j]){
                float f = 1.0f/rs[j];
                #pragma unroll
                for (int k=0;k<WAYS;k++) p[j][k] *= f;
            }
        }
        float cs[WAYS];
        #pragma unroll
        for (int k=0;k<WAYS;k++){
            float a = 0.0f;
            #pragma unroll
            for (int j=0;j<J;j++) if (valid[j]) a += p[j][k];
            cs[k] = a;
        }
        #pragma unroll
        for (int o=16;o;o>>=1){
            #pragma unroll
            for (int k=0;k<WAYS;k++) cs[k] += __shfl_xor_sync(0xffffffffu, cs[k], o);
        }
        #pragma unroll
        for (int k=0;k<WAYS;k++){
            float f = cval/cs[k];
            #pragma unroll
            for (int j=0;j<J;j++) if (valid[j]) p[j][k] *= f;
        }
        if (pin){
            #pragma unroll
            for (int k=0;k<WAYS;k++) p[0][k] = (k==ycls)?1.0f:0.0f;
        }
    }
}

// ================= K: zero bad flags ======================================
__global__ void k_zero(){
    int tid = threadIdx.x;
    for (int t=tid; t<4*1024; t+=256) g_bad[t]=0;
}

// ====== K: one-time raw 100x100 Gram (FFMA2) ==============================
__global__ void __launch_bounds__(256) k_gram(const float* __restrict__ xs,
                                              const float* __restrict__ xq){
    __shared__ float tile[64*TPW];
    int b = blockIdx.x, tid = threadIdx.x;
    int tx = tid & 15, ty = tid >> 4;
    u64t acc2[7][4];
    #pragma unroll
    for (int i=0;i<7;i++)
        #pragma unroll
        for (int e=0;e<4;e++) acc2[i][e] = pk2(0.f,0.f);
    for (int t=tid; t<64*TPW; t+=256) tile[t]=0.f;
    __syncthreads();
    const float* xsb = xs + (size_t)b*NSUP*DIM;
    const float* xqb = xq + (size_t)b*NQ*DIM;
    for (int c=0;c<10;c++){
        for (int t=tid; t<N100*64; t+=256){
            int row = t>>6, k = t&63;
            const float* fr = (row<NSUP) ? (xsb + (size_t)row*DIM)
                                         : (xqb + (size_t)(row-NSUP)*DIM);
            tile[k*TPW+row] = fr[c*64+k];
        }
        __syncthreads();
        #pragma unroll 2
        for (int k=0;k<64;k++){
            const float* tk = &tile[k*TPW];
            u64t ap[7], bp[4];
            #pragma unroll
            for (int i=0;i<7;i++){ float a = tk[ty+16*i]; ap[i]=pk2(a,a); }
            #pragma unroll
            for (int e=0;e<4;e++){
                float2 bv = *(const float2*)(tk + 2*tx + 32*e);
                bp[e] = pk2(bv.x, bv.y);
            }
            #pragma unroll
            for (int i=0;i<7;i++)
                #pragma unroll
                for (int e=0;e<4;e++) ffma2(acc2[i][e], ap[i], bp[e]);
        }
        __syncthreads();
    }
    float* G = g_G + (size_t)b*N100*N100;
    #pragma unroll
    for (int i=0;i<7;i++){
        int r = ty+16*i;
        if (r < N100){
            #pragma unroll
            for (int e=0;e<4;e++){
                int c = 2*tx+32*e;
                float2 g = upk2(acc2[i][e]);
                if (c   < N100) G[r*N100+c]   = g.x;
                if (c+1 < N100) G[r*N100+c+1] = g.y;
            }
        }
    }
}

// ---- shared helper: GC = G@c (500 entries), P = c^T GC (25 entries) ----
__device__ __forceinline__ void compute_GC_P(const float* __restrict__ G,
                                             const float* __restrict__ c,
                                             float* __restrict__ GC,
                                             float* __restrict__ P, int tid){
    for (int idx=tid; idx<N100*WAYS; idx+=256){
        int i = idx/WAYS, k = idx-WAYS*i;
        float s = 0.0f;
        #pragma unroll 10
        for (int j=0;j<N100;j++) s += G[i*N100+j]*c[j*WAYS+k];
        GC[idx] = s;
    }
    __syncthreads();
    if (tid < WAYS*WAYS){
        int a = tid/WAYS, bq = tid-WAYS*a;
        float s = 0.0f;
        #pragma unroll 10
        for (int i=0;i<N100;i++) s += c[i*WAYS+a]*GC[i*WAYS+bq];
        P[tid] = s;
    }
    __syncthreads();
}

// ================= K: c init + M(e0) + sinkA75(slot0) =====================
__global__ void __launch_bounds__(256) k_front(const int* __restrict__ ys){
    __shared__ float G[N100*N100];   // 40000
    __shared__ float c[N100*WAYS];   // 2000
    __shared__ float GC[N100*WAYS];  // 2000 (rows 25.. become M in place)
    __shared__ float P[WAYS*WAYS];
    int b = blockIdx.x, tid = threadIdx.x;
    int w = tid>>5, lane = tid&31;
    const float* Gg = g_G + (size_t)b*N100*N100;
    for (int t=tid; t<N100*N100; t+=256) G[t] = Gg[t];
    if (tid < N100){
        int cls = (tid < NSUP) ? ys[b*NSUP+tid] : -1;
        #pragma unroll
        for (int k=0;k<WAYS;k++) c[tid*WAYS+k] = (cls==k) ? 0.2f : 0.0f;
    }
    __syncthreads();
    compute_GC_P(G, c, GC, P, tid);
    // M in place over GC rows 25..99
    for (int t=tid; t<NQ*WAYS; t+=256){
        int r = t/WAYS, k = t-WAYS*r;
        int q = NSUP + r;
        float d2 = fmaxf(G[q*N100+q] + P[k*WAYS+k] - 2.0f*GC[q*WAYS+k], 0.0f);
        float m = __expf(-LAMv*d2);
        GC[q*WAYS+k] = m;
        g_M[(size_t)b*NQ*WAYS + t] = m;
    }
    float* Cg = g_C + (size_t)b*N100*WAYS;
    for (int t=tid; t<N100*WAYS; t+=256) Cg[t] = c[t];
    __syncthreads();
    if (w==0) sink_phaseA<NQ,0>(GC + NSUP*WAYS, (const int*)0, g_bad + 0*1024, lane);
}

// ===== K: sinkB75(slot_in) + c-update (+M(next)+sinkA75 | full: strip/Z) ===
__global__ void __launch_bounds__(256) k_mid(const int* __restrict__ ys,
                                             int slot_in, int slot_out, int full){
    __shared__ float G[N100*N100];                 // 40000
    __shared__ __align__(16) float z8[N100][8];    // 3200
    __shared__ float buf[N100*WAYS];               // 2000: zq early, GC later
    __shared__ float c[N100*WAYS];                 // 2000
    __shared__ float entm[N100];
    __shared__ float S[WAYS];
    __shared__ float P[WAYS*WAYS];
    __shared__ float dpe[WAYS*WAYS];
    __shared__ float maskv[WAYS];
    __shared__ float omega_s;
    int b = blockIdx.x, tid = threadIdx.x;
    int w = tid>>5, lane = tid&31;
    const float INVLOG5 = 0.6213349345596119f;

    const float* Gg = g_G + (size_t)b*N100*N100;
    for (int t=tid; t<N100*N100; t+=256) G[t] = Gg[t];

    if (w==0){
        float p[(NQ+31)/32][WAYS];
        sink_phaseB<NQ,0>(g_M + (size_t)b*NQ*WAYS, (const int*)0,
                          g_bad + slot_in*1024, lane, p);
        #pragma unroll
        for (int j=0;j<(NQ+31)/32;j++){
            int r = lane+32*j;
            if (r<NQ){
                #pragma unroll
                for (int k=0;k<WAYS;k++) buf[r*WAYS+k] = p[j][k];
            }
        }
    }
    __syncthreads();

    if (tid < N100){
        float zv[WAYS];
        if (tid < NSUP){
            int cls = ys[b*NSUP + tid];
            #pragma unroll
            for (int k=0;k<WAYS;k++) zv[k] = (k==cls)?1.0f:0.0f;
        } else {
            #pragma unroll
            for (int k=0;k<WAYS;k++) zv[k] = buf[(tid-NSUP)*WAYS+k];
        }
        float q[WAYS]; float s = 0.0f;
        #pragma unroll
        for (int k=0;k<WAYS;k++){ q[k] = zv[k] + 1e-12f; s += q[k]; }
        float H = 0.0f;
        #pragma unroll
        for (int k=0;k<WAYS;k++){ float pp = q[k]/s; H -= pp*logf(pp); }
        float e = H*INVLOG5;
        entm[tid] = e;
        float wgt = 1.0f - e;
        #pragma unroll
        for (int k=0;k<WAYS;k++) z8[tid][k] = zv[k]*wgt;
        z8[tid][5]=0.f; z8[tid][6]=0.f; z8[tid][7]=0.f;
    }
    __syncthreads();
    if (tid < WAYS){
        float a = 0.0f;
        for (int i=0;i<N100;i++) a += z8[i][tid];
        S[tid] = a;
    }
    if (tid == 128){
        float a = 0.0f;
        for (int i=0;i<N100;i++) a += entm[i];
        omega_s = a*0.01f;
    }
    __syncthreads();
    // coefficient update: c = 0.4*c_old + 0.6*z8/S
    float* Cg = g_C + (size_t)b*N100*WAYS;
    if (tid < N100){
        #pragma unroll
        for (int k=0;k<WAYS;k++){
            float nv = 0.4f*Cg[tid*WAYS+k] + 0.6f*(z8[tid][k]/S[k]);
            c[tid*WAYS+k] = nv;
        }
    }
    __syncthreads();
    for (int t=tid; t<N100*WAYS; t+=256) Cg[t] = c[t];
    compute_GC_P(G, c, buf, P, tid);   // buf = GC now

    if (full){
        if (tid < WAYS*WAYS){
            int a = tid/WAYS, q2 = tid-WAYS*a;
            float d2 = fmaxf(P[a*WAYS+a] + P[q2*WAYS+q2] - 2.0f*P[tid], 0.0f);
            dpe[tid] = __expf(-LAMv*d2);
        }
        __syncthreads();
        if (tid < WAYS){
            float q[WAYS]; float s = 0.0f;
            #pragma unroll
            for (int k=0;k<WAYS;k++){ q[k] = dpe[tid*WAYS+k] + 1e-12f; s += q[k]; }
            float H = 0.0f;
            #pragma unroll
            for (int k=0;k<WAYS;k++){ float pp = q[k]/s; H -= pp*logf(pp); }
            maskv[tid] = (H*INVLOG5 < omega_s) ? 1.0f : 0.0f;
        }
        __syncthreads();
        float* Zb = g_Z + (size_t)b*N105*WAYS;
        float* Sb = g_S + (size_t)b*N105*WAYS;
        for (int t=tid; t<N100*WAYS; t+=256){
            Zb[t] = z8[t/WAYS][t%WAYS];
            Sb[t] = maskv[t%WAYS]*buf[t];          // strip = mask_p * GC[:,p]
        }
        if (tid < WAYS*WAYS){
            Zb[N100*WAYS + tid] = dpe[tid]*maskv[tid/WAYS];
            Sb[N100*WAYS + tid] = maskv[tid/WAYS]*maskv[tid%WAYS]*P[tid];
        }
        return;
    }

    // M for next epoch, in place over GC rows 25..99
    for (int t=tid; t<NQ*WAYS; t+=256){
        int r = t/WAYS, k = t-WAYS*r;
        int q = NSUP + r;
        float d2 = fmaxf(G[q*N100+q] + P[k*WAYS+k] - 2.0f*buf[q*WAYS+k], 0.0f);
        float m = __expf(-LAMv*d2);
        buf[q*WAYS+k] = m;
        g_M[(size_t)b*NQ*WAYS + t] = m;
    }
    __syncthreads();
    if (w==0) sink_phaseA<NQ,0>(buf + NSUP*WAYS, (const int*)0, g_bad + slot_out*1024, lane);
}

// ====== K: G+strip -> W -> A=I-aW -> blocked LU + sinkA105(slot3) =========
__global__ void __launch_bounds__(256) k_solve(const int* __restrict__ ys){
    __shared__ float As[N105*N105];   // 44100
    __shared__ float zz[N105*WAYS];   // 2100
    __shared__ float st[N105*WAYS];   // 2100
    __shared__ float nn[N105];        // 420
    __shared__ float dm[N105];        // 420   total 49140
    int b = blockIdx.x, tid = threadIdx.x;
    int w = tid>>5, lane = tid&31;

    const float* Gg = g_G + (size_t)b*N100*N100;
    const float* Sb = g_S + (size_t)b*N105*WAYS;
    for (int t=tid; t<N105*WAYS; t+=256) st[t] = Sb[t];
    __syncthreads();
    if (tid < N100) nn[tid] = Gg[tid*N100+tid];
    else if (tid < N105) nn[tid] = st[tid*WAYS + (tid-N100)];
    __syncthreads();
    // assemble W
    for (int t=tid; t<N105*N105; t+=256){
        int i = t/N105, j = t - i*N105;
        float v;
        if (i == j){
            v = 0.0f;
        } else {
            float dot;
            if (i < N100 && j < N100)      dot = Gg[i*N100+j];
            else if (i < N100)             dot = st[i*WAYS + (j-N100)];
            else if (j < N100)             dot = st[j*WAYS + (i-N100)];
            else                           dot = st[i*WAYS + (j-N100)];
            float d2 = fmaxf(nn[i] + nn[j] - 2.0f*dot, 0.0f);
            v = __expf(-LAMv*d2);
        }
        As[t] = v;
    }
    float* Zb = g_Z + (size_t)b*N105*WAYS;
    for (int t=tid; t<N105*WAYS; t+=256) zz[t] = Zb[t];
    __syncthreads();

    if (tid < N105){
        float s = 0.0f;
        for (int j=0;j<N105;j++) s += As[tid*N105+j];
        dm[tid] = rsqrtf(s);
    }
    __syncthreads();
    for (int t=tid; t<N105*N105; t+=256){
        int i = t/N105, j = t - i*N105;
        As[t] = ((i==j)?1.0f:0.0f) - 0.7f*dm[i]*dm[j]*As[t];
    }
    __syncthreads();

    // ---- rank-4 blocked LU forward elimination ----
    for (int K=0; K<26; K++){
        const int k0 = 4*K;
        if (w==0){
            #pragma unroll
            for (int kk=0; kk<4; kk++){
                int pc = k0+kk;
                float inv = 1.0f/As[pc*N105+pc];
                for (int i=pc+1+lane; i<N105; i+=32){
                    float l = As[i*N105+pc]*inv;
                    As[i*N105+pc] = l;
                    #pragma unroll
                    for (int c2=kk+1; c2<4; c2++)
                        As[i*N105+k0+c2] -= l*As[pc*N105+k0+c2];
                }
                __syncwarp();
            }
        }
        __syncthreads();
        float l10=As[(k0+1)*N105+k0];
        float l20=As[(k0+2)*N105+k0], l21=As[(k0+2)*N105+k0+1];
        float l30=As[(k0+3)*N105+k0], l31=As[(k0+3)*N105+k0+1], l32=As[(k0+3)*N105+k0+2];
        for (int j=k0+4+tid; j<N105; j+=256){
            float a0=As[(k0+0)*N105+j], a1=As[(k0+1)*N105+j];
            float a2=As[(k0+2)*N105+j], a3=As[(k0+3)*N105+j];
            a1 -= l10*a0;
            a2 -= l20*a0 + l21*a1;
            a3 -= l30*a0 + l31*a1 + l32*a2;
            As[(k0+1)*N105+j]=a1; As[(k0+2)*N105+j]=a2; As[(k0+3)*N105+j]=a3;
        }
        if (tid < WAYS){
            float a0=zz[(k0+0)*WAYS+tid], a1=zz[(k0+1)*WAYS+tid];
            float a2=zz[(k0+2)*WAYS+tid], a3=zz[(k0+3)*WAYS+tid];
            a1 -= l10*a0;
            a2 -= l20*a0 + l21*a1;
            a3 -= l30*a0 + l31*a1 + l32*a2;
            zz[(k0+1)*WAYS+tid]=a1; zz[(k0+2)*WAYS+tid]=a2; zz[(k0+3)*WAYS+tid]=a3;
        }
        __syncthreads();
        const int j0 = k0+4+lane;
        float u0[4], u1[4], u2[4], u3[4], uz0,uz1,uz2,uz3;
        #pragma unroll
        for (int e=0;e<4;e++){
            int j = j0+32*e;
            bool ok = (j<N105);
            u0[e] = ok ? As[(k0+0)*N105+j] : 0.0f;
            u1[e] = ok ? As[(k0+1)*N105+j] : 0.0f;
            u2[e] = ok ? As[(k0+2)*N105+j] : 0.0f;
            u3[e] = ok ? As[(k0+3)*N105+j] : 0.0f;
        }
        uz0 = (lane<WAYS)? zz[(k0+0)*WAYS+lane] : 0.0f;
        uz1 = (lane<WAYS)? zz[(k0+1)*WAYS+lane] : 0.0f;
        uz2 = (lane<WAYS)? zz[(k0+2)*WAYS+lane] : 0.0f;
        uz3 = (lane<WAYS)? zz[(k0+3)*WAYS+lane] : 0.0f;
        for (int i=k0+4+w; i<N105; i+=8){
            float l0=As[i*N105+k0+0], l1=As[i*N105+k0+1];
            float l2=As[i*N105+k0+2], l3=As[i*N105+k0+3];
            #pragma unroll
            for (int e=0;e<4;e++){
                int j = j0+32*e;
                if (j<N105)
                    As[i*N105+j] -= l0*u0[e]+l1*u1[e]+l2*u2[e]+l3*u3[e];
            }
            if (lane<WAYS)
                zz[i*WAYS+lane] -= l0*uz0+l1*uz1+l2*uz2+l3*uz3;
        }
        __syncthreads();
    }

    // ---- blocked back substitution ----
    if (tid < WAYS) zz[104*WAYS+tid] /= As[104*N105+104];
    __syncthreads();
    for (int t=tid; t<104*WAYS; t+=256){
        int i=t/WAYS, m=t-i*WAYS;
        zz[t] -= As[i*N105+104]*zz[104*WAYS+m];
    }
    __syncthreads();
    for (int K=25; K>=0; K--){
        const int lo = 4*K, hi = lo+3;
        if (w==0 && lane<WAYS){
            for (int r=hi; r>=lo; r--){
                float acc = zz[r*WAYS+lane];
                for (int c2=r+1; c2<=hi; c2++) acc -= As[r*N105+c2]*zz[c2*WAYS+lane];
                zz[r*WAYS+lane] = acc / As[r*N105+r];
            }
        }
        __syncthreads();
        if (lo > 0){
            for (int t=tid; t<lo*WAYS; t+=256){
                int i=t/WAYS, m=t-i*WAYS;
                float s = As[i*N105+lo+0]*zz[(lo+0)*WAYS+m]
                        + As[i*N105+lo+1]*zz[(lo+1)*WAYS+m]
                        + As[i*N105+lo+2]*zz[(lo+2)*WAYS+m]
                        + As[i*N105+lo+3]*zz[(lo+3)*WAYS+m];
                zz[t] -= s;
            }
        }
        __syncthreads();
    }
    for (int t=tid; t<N105*WAYS; t+=256) Zb[t] = zz[t];
    __syncthreads();
    if (w==0) sink_phaseA<N105,NSUP>(zz, ys + b*NSUP, g_bad + 3*1024, lane);
}

// ================= K: sinkB105(slot3) + accuracy ==========================
__global__ void __launch_bounds__(128) k_final(const int* __restrict__ ys,
                                               const int* __restrict__ yq,
                                               float* __restrict__ out){
    int gw = blockIdx.x*4 + (threadIdx.x>>5);
    int lane = threadIdx.x & 31;
    if (gw >= RUNS) return;
    int b = gw;
    float p[(N105+31)/32][WAYS];
    sink_phaseB<N105,NSUP>(g_Z + (size_t)b*N105*WAYS, ys + b*NSUP,
                           g_bad + 3*1024, lane, p);
    int cnt = 0;
    #pragma unroll
    for (int j=0;j<(N105+31)/32;j++){
        int r = lane + 32*j;
        if (r >= NSUP && r < N100){
            float best = p[j][0]; int bi = 0;
            #pragma unroll
            for (int k=1;k<WAYS;k++){ if (p[j][k] > best){ best = p[j][k]; bi = k; } }
            cnt += (bi == yq[b*NQ + (r-NSUP)]) ? 1 : 0;
        }
    }
    #pragma unroll
    for (int o=16;o;o>>=1) cnt += __shfl_xor_sync(0xffffffffu, cnt, o);
    if (lane==0) out[b] = (float)cnt / 75.0f;
}

extern "C" void kernel_launch(void* const* d_in, const int* in_sizes, int n_in,
                              void* d_out, int out_size){
    const float* xs = (const float*)d_in[0];
    const float* xq = (const float*)d_in[1];
    const int*   ys = (const int*)d_in[2];
    const int*   yq = (const int*)d_in[3];
    float* out = (float*)d_out;
    (void)in_sizes; (void)n_in; (void)out_size;

    k_zero<<<1,256>>>();                       // 0
    k_gram<<<RUNS,256>>>(xs, xq);              // 1: raw G (only feature reader)
    k_front<<<RUNS,256>>>(ys);                 // 2: c init + M(e0) + sinkA s0
    k_mid<<<RUNS,256>>>(ys, 0, 1, 0);          // 3
    k_mid<<<RUNS,256>>>(ys, 1, 2, 0);          // 4
    k_mid<<<RUNS,256>>>(ys, 2, 0, 1);          // 5: full -> strip/Z
    k_solve<<<RUNS,256>>>(ys);                 // 6
    k_final<<<RUNS/4,128>>>(ys, yq, out);      // 7
}